// round 1
// baseline (speedup 1.0000x reference)
#include <cuda_runtime.h>
#include <math.h>

#define K_DIM   2048
#define N_DIM   160
#define NC      10
#define DC      16
#define BM      128
#define BK      16
#define NTHREAD 256
#define HAT_STRIDE 165   // 160 + 5 (gcd(5,32)=1 -> conflict-free per-row access)

// ---- packed f32x2 helpers (Blackwell FFMA2: 2 MACs / instruction) ----
__device__ __forceinline__ unsigned long long pack2(float x, float y) {
    unsigned long long r;
    asm("mov.b64 %0, {%1, %2};" : "=l"(r) : "f"(x), "f"(y));
    return r;
}
__device__ __forceinline__ void fma2(unsigned long long& d,
                                     unsigned long long a,
                                     unsigned long long b) {
    asm("fma.rn.f32x2 %0, %1, %2, %0;" : "+l"(d) : "l"(a), "l"(b));
}
__device__ __forceinline__ float2 unpack2(unsigned long long v) {
    float2 f;
    f.x = __uint_as_float((unsigned int)(v & 0xFFFFFFFFull));
    f.y = __uint_as_float((unsigned int)(v >> 32));
    return f;
}

__global__ void __launch_bounds__(NTHREAD, 1)
caps_fused_kernel(const float* __restrict__ inp,   // [rows, 2048]
                  const float* __restrict__ wk,    // [2048, 160]
                  float* __restrict__ dout,        // [rows, 16]
                  int rows)
{
    extern __shared__ float smem[];
    float* As  = smem;                         // BM*BK   = 2048 floats
    float* Bs  = smem + BM * BK;               // BK*N    = 2560 floats
    float* hat = Bs + BK * N_DIM;              // BM*HAT_STRIDE floats

    const int tid = threadIdx.x;
    const int cg  = tid & 15;   // column group 0..15
    const int rg  = tid >> 4;   // row group    0..15
    const int rowBase = blockIdx.x * BM;

    const float4* Ag  = reinterpret_cast<const float4*>(inp);
    const float2* Bg  = reinterpret_cast<const float2*>(wk);
    float4* As4 = reinterpret_cast<float4*>(As);
    float2* Bs2 = reinterpret_cast<float2*>(Bs);

    const int ar0  = tid >> 2;   // A-load row within tile (0..63)
    const int aseg = tid & 3;    // which float4 within the 16-float chunk row

    // 8 rows x 5 col-pairs of f32x2 accumulators
    unsigned long long acc[8][5];
    #pragma unroll
    for (int r = 0; r < 8; ++r)
        #pragma unroll
        for (int j = 0; j < 5; ++j)
            acc[r][j] = 0ull;

    const size_t aStride4 = K_DIM / 4;   // float4 per input row
    const int    bChunk2  = BK * (N_DIM / 2); // float2 per kernel chunk = 1280

    float4 ra0, ra1;
    float2 rb[5];

    // ---- prologue: load chunk 0 into registers, commit to smem ----
    {
        ra0 = Ag[(size_t)(rowBase + ar0)       * aStride4 + aseg];
        ra1 = Ag[(size_t)(rowBase + ar0 + 64)  * aStride4 + aseg];
        #pragma unroll
        for (int i = 0; i < 5; ++i)
            rb[i] = Bg[(size_t)tid + 256 * i];
    }
    As4[tid]       = ra0;
    As4[tid + 256] = ra1;
    #pragma unroll
    for (int i = 0; i < 5; ++i)
        Bs2[tid + 256 * i] = rb[i];
    __syncthreads();

    const int NCHUNK = K_DIM / BK;  // 128
    for (int c = 0; c < NCHUNK; ++c) {
        const bool has_next = (c + 1) < NCHUNK;
        if (has_next) {
            const int k4 = (c + 1) * (BK / 4);
            ra0 = Ag[(size_t)(rowBase + ar0)      * aStride4 + k4 + aseg];
            ra1 = Ag[(size_t)(rowBase + ar0 + 64) * aStride4 + k4 + aseg];
            const size_t bb = (size_t)(c + 1) * bChunk2;
            #pragma unroll
            for (int i = 0; i < 5; ++i)
                rb[i] = Bg[bb + tid + 256 * i];
        }

        // ---- compute on current smem chunk ----
        #pragma unroll
        for (int kk = 0; kk < BK; ++kk) {
            unsigned long long av[8];
            #pragma unroll
            for (int r = 0; r < 8; ++r) {
                float a = As[(rg * 8 + r) * BK + kk];   // broadcast across 16 lanes
                av[r] = pack2(a, a);
            }
            unsigned long long bv[5];
            #pragma unroll
            for (int j = 0; j < 5; ++j) {
                float2 b2 = Bs2[kk * (N_DIM / 2) + cg + 16 * j];  // conflict-free LDS.64
                bv[j] = pack2(b2.x, b2.y);
            }
            #pragma unroll
            for (int r = 0; r < 8; ++r)
                #pragma unroll
                for (int j = 0; j < 5; ++j)
                    fma2(acc[r][j], av[r], bv[j]);
        }
        __syncthreads();

        if (has_next) {
            As4[tid]       = ra0;
            As4[tid + 256] = ra1;
            #pragma unroll
            for (int i = 0; i < 5; ++i)
                Bs2[tid + 256 * i] = rb[i];
        }
        __syncthreads();
    }

    // ---- spill inputs_hat tile to padded smem ----
    #pragma unroll
    for (int r = 0; r < 8; ++r) {
        const int row = rg * 8 + r;
        #pragma unroll
        for (int j = 0; j < 5; ++j) {
            float2 v = unpack2(acc[r][j]);
            const int p = cg + 16 * j;            // col pair index
            hat[row * HAT_STRIDE + 2 * p]     = v.x;
            hat[row * HAT_STRIDE + 2 * p + 1] = v.y;
        }
    }
    __syncthreads();

    // ---- dynamic routing: one thread per row ----
    if (tid < BM) {
        const float* h = &hat[tid * HAT_STRIDE];   // [NC][DC] for this row

        float b[NC];
        #pragma unroll
        for (int n = 0; n < NC; ++n) b[n] = 0.0f;

        float out[DC];

        #pragma unroll
        for (int it = 0; it < 3; ++it) {
            // softmax over capsules
            float m = b[0];
            #pragma unroll
            for (int n = 1; n < NC; ++n) m = fmaxf(m, b[n]);
            float cc[NC];
            float se = 0.0f;
            #pragma unroll
            for (int n = 0; n < NC; ++n) { cc[n] = expf(b[n] - m); se += cc[n]; }
            const float inv = 1.0f / se;

            // s = sum_n c[n] * hat[n, :]
            float s[DC];
            #pragma unroll
            for (int d = 0; d < DC; ++d) s[d] = 0.0f;
            #pragma unroll
            for (int n = 0; n < NC; ++n) {
                const float cn = cc[n] * inv;
                #pragma unroll
                for (int d = 0; d < DC; ++d)
                    s[d] = fmaf(cn, h[n * DC + d], s[d]);
            }

            // squash
            float s2 = 0.0f;
            #pragma unroll
            for (int d = 0; d < DC; ++d) s2 = fmaf(s[d], s[d], s2);
            const float scale = s2 / ((1.0f + s2) * sqrtf(s2 + 1e-7f));
            #pragma unroll
            for (int d = 0; d < DC; ++d) out[d] = scale * s[d];

            // b[n] += dot(hat[n,:], out)
            if (it < 2) {
                #pragma unroll
                for (int n = 0; n < NC; ++n) {
                    float dot = 0.0f;
                    #pragma unroll
                    for (int d = 0; d < DC; ++d)
                        dot = fmaf(h[n * DC + d], out[d], dot);
                    b[n] += dot;
                }
            }
        }

        float* o = dout + (size_t)(rowBase + tid) * DC;
        #pragma unroll
        for (int d = 0; d < DC; ++d) o[d] = out[d];
    }
}

extern "C" void kernel_launch(void* const* d_in, const int* in_sizes, int n_in,
                              void* d_out, int out_size)
{
    const float* inp = (const float*)d_in[0];
    const float* wk  = (const float*)d_in[1];
    float* out       = (float*)d_out;

    const int rows = in_sizes[0] / K_DIM;  // 16384
    const int smem_bytes = (BM * BK + BK * N_DIM + BM * HAT_STRIDE) * (int)sizeof(float);

    cudaFuncSetAttribute(caps_fused_kernel,
                         cudaFuncAttributeMaxDynamicSharedMemorySize, smem_bytes);

    caps_fused_kernel<<<rows / BM, NTHREAD, smem_bytes>>>(inp, wk, out, rows);
}

// round 3
// speedup vs baseline: 1.7977x; 1.7977x over previous
#include <cuda_runtime.h>
#include <cuda_bf16.h>
#include <math.h>
#include <stdint.h>

#define K_DIM   2048
#define N_DIM   160
#define NC      10
#define DC      16
#define BM      64
#define BK      32
#define NCHUNK  (K_DIM / BK)          // 64
#define NTHREAD 256
#define HAT_STRIDE 165

// stage layout (bytes), rows padded to 80B for conflict-free ldmatrix
#define A_HI    0
#define A_LO    5120
#define B_HI    10240
#define B_LO    23040
#define STAGE_BYTES 35840
#define SMEM_TOTAL  (2 * STAGE_BYTES)   // 71680

// Precomputed transposed split weights: Wt[n][k] = W[k][n]
__device__ __nv_bfloat16 g_Wt_hi[N_DIM * K_DIM];
__device__ __nv_bfloat16 g_Wt_lo[N_DIM * K_DIM];

// ---------------- helpers ----------------
__device__ __forceinline__ uint32_t smem_u32(const void* p) {
    uint32_t a;
    asm("{ .reg .u64 t; cvta.to.shared.u64 t, %1; cvt.u32.u64 %0, t; }" : "=r"(a) : "l"(p));
    return a;
}
__device__ __forceinline__ void ldsm4(uint32_t* d, uint32_t addr) {
    asm volatile("ldmatrix.sync.aligned.m8n8.x4.shared.b16 {%0,%1,%2,%3}, [%4];"
                 : "=r"(d[0]), "=r"(d[1]), "=r"(d[2]), "=r"(d[3]) : "r"(addr));
}
__device__ __forceinline__ void mma16816(float* c, const uint32_t* a,
                                         uint32_t b0, uint32_t b1) {
    asm volatile("mma.sync.aligned.m16n8k16.row.col.f32.bf16.bf16.f32 "
                 "{%0,%1,%2,%3}, {%4,%5,%6,%7}, {%8,%9}, {%0,%1,%2,%3};"
                 : "+f"(c[0]), "+f"(c[1]), "+f"(c[2]), "+f"(c[3])
                 : "r"(a[0]), "r"(a[1]), "r"(a[2]), "r"(a[3]), "r"(b0), "r"(b1));
}
__device__ __forceinline__ void cp_async16(uint32_t smem_dst, const void* gsrc) {
    asm volatile("cp.async.cg.shared.global [%0], [%1], 16;"
                 :: "r"(smem_dst), "l"(__cvta_generic_to_global(gsrc)) : "memory");
}
#define CP_COMMIT() asm volatile("cp.async.commit_group;" ::: "memory")
#define CP_WAIT0()  asm volatile("cp.async.wait_group 0;" ::: "memory")

__device__ __forceinline__ uint32_t pack_bf2(float x, float y) {
    __nv_bfloat162 t(__float2bfloat16(x), __float2bfloat16(y));
    return *reinterpret_cast<uint32_t*>(&t);
}

// ---------------- pre-kernel: split + transpose W ----------------
__global__ void wt_split_kernel(const float* __restrict__ wk) {
    int idx = blockIdx.x * 256 + threadIdx.x;
    if (idx < N_DIM * K_DIM) {
        int n = idx / K_DIM;
        int k = idx % K_DIM;
        float v = wk[(size_t)k * N_DIM + n];
        __nv_bfloat16 hi = __float2bfloat16(v);
        g_Wt_hi[idx] = hi;
        g_Wt_lo[idx] = __float2bfloat16(v - __bfloat162float(hi));
    }
}

// ---------------- main fused kernel ----------------
__global__ void __launch_bounds__(NTHREAD, 2)
caps_hmma_kernel(const float* __restrict__ inp, float* __restrict__ dout, int rows)
{
    extern __shared__ char smem[];
    const uint32_t sb = smem_u32(smem);
    const int tid  = threadIdx.x;
    const int lane = tid & 31;
    const int w    = tid >> 5;
    const int rowBase = blockIdx.x * BM;

    // warp tiling: 4 M-groups x 2 N-groups
    const int m0 = (w >> 1) * 16;
    const int n0 = (w & 1) * 80;

    // ldmatrix per-lane address offsets (byte offsets within arrays, rows stride 80B)
    const int rA = (lane & 7) + ((lane >> 3) & 1) * 8;
    const int cA = (lane >> 4) * 16;
    const int aoff = (m0 + rA) * 80 + cA;

    const int rB = (lane & 7) + ((lane >> 4) ? 8 : 0);
    const int cB = ((lane >> 3) & 1) * 16;
    const int boff = (n0 + rB) * 80 + cB;

    float acc[10][4];
    #pragma unroll
    for (int j = 0; j < 10; ++j)
        #pragma unroll
        for (int e = 0; e < 4; ++e) acc[j][e] = 0.0f;

    // A global-load mapping: 2 float4 per thread per chunk
    const int arow0 = tid >> 3;          // 0..31
    const int aseg  = tid & 7;           // float4 index within 32-fp32 row chunk

    // ---- prologue: fill stage 0 with chunk 0 ----
    {
        char* st = smem;
        const uint32_t stu = sb;
        #pragma unroll
        for (int i = 0; i < 2; ++i) {
            const int row = arow0 + 32 * i;
            float4 v = *reinterpret_cast<const float4*>(
                inp + (size_t)(rowBase + row) * K_DIM + aseg * 4);
            uint2 hp = make_uint2(pack_bf2(v.x, v.y), pack_bf2(v.z, v.w));
            float lx = v.x - __bfloat162float(__float2bfloat16(v.x));
            float ly = v.y - __bfloat162float(__float2bfloat16(v.y));
            float lz = v.z - __bfloat162float(__float2bfloat16(v.z));
            float lw = v.w - __bfloat162float(__float2bfloat16(v.w));
            uint2 lp = make_uint2(pack_bf2(lx, ly), pack_bf2(lz, lw));
            *reinterpret_cast<uint2*>(st + A_HI + row * 80 + aseg * 8) = hp;
            *reinterpret_cast<uint2*>(st + A_LO + row * 80 + aseg * 8) = lp;
        }
        #pragma unroll
        for (int i = 0; i < 5; ++i) {
            const int u = tid + 256 * i;          // 0..1279
            const int isLo = (u >= 640);
            const int r = isLo ? (u - 640) : u;
            const int n = r >> 2, seg = r & 3;
            const __nv_bfloat16* src = (isLo ? g_Wt_lo : g_Wt_hi) +
                                       (size_t)n * K_DIM + seg * 8;
            cp_async16(stu + (isLo ? B_LO : B_HI) + n * 80 + seg * 16, src);
        }
        CP_COMMIT();
        CP_WAIT0();
    }
    __syncthreads();

    // ---- main loop ----
    for (int c = 0; c < NCHUNK; ++c) {
        const int s = c & 1;
        const uint32_t cur = sb + s * STAGE_BYTES;
        const uint32_t nxt = sb + (s ^ 1) * STAGE_BYTES;
        char* nxtp = smem + (s ^ 1) * STAGE_BYTES;

        float4 ra[2];
        if (c + 1 < NCHUNK) {
            const int kbase = (c + 1) * BK;
            #pragma unroll
            for (int i = 0; i < 2; ++i) {
                const int row = arow0 + 32 * i;
                ra[i] = *reinterpret_cast<const float4*>(
                    inp + (size_t)(rowBase + row) * K_DIM + kbase + aseg * 4);
            }
            #pragma unroll
            for (int i = 0; i < 5; ++i) {
                const int u = tid + 256 * i;
                const int isLo = (u >= 640);
                const int r = isLo ? (u - 640) : u;
                const int n = r >> 2, seg = r & 3;
                const __nv_bfloat16* src = (isLo ? g_Wt_lo : g_Wt_hi) +
                                           (size_t)n * K_DIM + kbase + seg * 8;
                cp_async16(nxt + (isLo ? B_LO : B_HI) + n * 80 + seg * 16, src);
            }
            CP_COMMIT();
        }

        // ---- compute chunk c ----
        const uint32_t ah_base = cur + A_HI + aoff;
        const uint32_t al_base = cur + A_LO + aoff;
        const uint32_t bh_base = cur + B_HI + boff;
        const uint32_t bl_base = cur + B_LO + boff;
        #pragma unroll
        for (int ks = 0; ks < 2; ++ks) {
            uint32_t ah[4], al[4];
            ldsm4(ah, ah_base + ks * 32);
            ldsm4(al, al_base + ks * 32);
            #pragma unroll
            for (int g = 0; g < 5; ++g) {
                uint32_t bh[4], bl[4];
                ldsm4(bh, bh_base + g * 1280 + ks * 32);
                ldsm4(bl, bl_base + g * 1280 + ks * 32);
                mma16816(acc[2 * g],     ah, bh[0], bh[1]);
                mma16816(acc[2 * g],     al, bh[0], bh[1]);
                mma16816(acc[2 * g],     ah, bl[0], bl[1]);
                mma16816(acc[2 * g + 1], ah, bh[2], bh[3]);
                mma16816(acc[2 * g + 1], al, bh[2], bh[3]);
                mma16816(acc[2 * g + 1], ah, bl[2], bl[3]);
            }
        }

        if (c + 1 < NCHUNK) {
            #pragma unroll
            for (int i = 0; i < 2; ++i) {
                const int row = arow0 + 32 * i;
                float4 v = ra[i];
                uint2 hp = make_uint2(pack_bf2(v.x, v.y), pack_bf2(v.z, v.w));
                float lx = v.x - __bfloat162float(__float2bfloat16(v.x));
                float ly = v.y - __bfloat162float(__float2bfloat16(v.y));
                float lz = v.z - __bfloat162float(__float2bfloat16(v.z));
                float lw = v.w - __bfloat162float(__float2bfloat16(v.w));
                uint2 lp = make_uint2(pack_bf2(lx, ly), pack_bf2(lz, lw));
                *reinterpret_cast<uint2*>(nxtp + A_HI + row * 80 + aseg * 8) = hp;
                *reinterpret_cast<uint2*>(nxtp + A_LO + row * 80 + aseg * 8) = lp;
            }
            CP_WAIT0();
        }
        __syncthreads();
    }

    // ---- write C frags to padded smem hat tile ----
    float* hat = reinterpret_cast<float*>(smem);
    {
        const int r0 = m0 + (lane >> 2);
        const int cbase = n0 + (lane & 3) * 2;
        #pragma unroll
        for (int j = 0; j < 10; ++j) {
            const int col = cbase + 8 * j;
            hat[r0 * HAT_STRIDE + col]           = acc[j][0];
            hat[r0 * HAT_STRIDE + col + 1]       = acc[j][1];
            hat[(r0 + 8) * HAT_STRIDE + col]     = acc[j][2];
            hat[(r0 + 8) * HAT_STRIDE + col + 1] = acc[j][3];
        }
    }
    __syncthreads();

    // ---- dynamic routing: one thread per row ----
    if (tid < BM) {
        const float* h = &hat[tid * HAT_STRIDE];

        float b[NC];
        #pragma unroll
        for (int n = 0; n < NC; ++n) b[n] = 0.0f;
        float out[DC];

        #pragma unroll
        for (int it = 0; it < 3; ++it) {
            float m = b[0];
            #pragma unroll
            for (int n = 1; n < NC; ++n) m = fmaxf(m, b[n]);
            float cc[NC];
            float se = 0.0f;
            #pragma unroll
            for (int n = 0; n < NC; ++n) { cc[n] = expf(b[n] - m); se += cc[n]; }
            const float inv = 1.0f / se;

            float s[DC];
            #pragma unroll
            for (int d = 0; d < DC; ++d) s[d] = 0.0f;
            #pragma unroll
            for (int n = 0; n < NC; ++n) {
                const float cn = cc[n] * inv;
                #pragma unroll
                for (int d = 0; d < DC; ++d)
                    s[d] = fmaf(cn, h[n * DC + d], s[d]);
            }

            float s2 = 0.0f;
            #pragma unroll
            for (int d = 0; d < DC; ++d) s2 = fmaf(s[d], s[d], s2);
            const float scale = s2 / ((1.0f + s2) * sqrtf(s2 + 1e-7f));
            #pragma unroll
            for (int d = 0; d < DC; ++d) out[d] = scale * s[d];

            if (it < 2) {
                #pragma unroll
                for (int n = 0; n < NC; ++n) {
                    float dot = 0.0f;
                    #pragma unroll
                    for (int d = 0; d < DC; ++d)
                        dot = fmaf(h[n * DC + d], out[d], dot);
                    b[n] += dot;
                }
            }
        }

        float4* o = reinterpret_cast<float4*>(dout + (size_t)(rowBase + tid) * DC);
        o[0] = make_float4(out[0],  out[1],  out[2],  out[3]);
        o[1] = make_float4(out[4],  out[5],  out[6],  out[7]);
        o[2] = make_float4(out[8],  out[9],  out[10], out[11]);
        o[3] = make_float4(out[12], out[13], out[14], out[15]);
    }
}

extern "C" void kernel_launch(void* const* d_in, const int* in_sizes, int n_in,
                              void* d_out, int out_size)
{
    const float* inp = (const float*)d_in[0];
    const float* wk  = (const float*)d_in[1];
    float* out       = (float*)d_out;

    const int rows = in_sizes[0] / K_DIM;   // 16384

    wt_split_kernel<<<(N_DIM * K_DIM + 255) / 256, 256>>>(wk);

    cudaFuncSetAttribute(caps_hmma_kernel,
                         cudaFuncAttributeMaxDynamicSharedMemorySize, SMEM_TOTAL);
    caps_hmma_kernel<<<rows / BM, NTHREAD, SMEM_TOTAL>>>(inp, out, rows);
}

// round 4
// speedup vs baseline: 1.9405x; 1.0795x over previous
#include <cuda_runtime.h>
#include <cuda_bf16.h>
#include <math.h>
#include <stdint.h>

#define K_DIM   2048
#define N_DIM   160
#define NC      10
#define DC      16
#define BM      128
#define BK      32
#define NCHUNK  (K_DIM / BK)          // 64
#define NTHREAD 256
#define HAT_STRIDE 165

// stage layout (bytes), rows padded to 80B for conflict-free ldmatrix
#define A_HI    0
#define A_LO    10240
#define B_HI    20480
#define B_LO    33280
#define STAGE_BYTES 46080
#define SMEM_TOTAL  (2 * STAGE_BYTES)   // 92160 (hat tile 128*165*4=84480 fits)

// Precomputed transposed split weights: Wt[n][k] = W[k][n]
__device__ __nv_bfloat16 g_Wt_hi[N_DIM * K_DIM];
__device__ __nv_bfloat16 g_Wt_lo[N_DIM * K_DIM];

// ---------------- helpers ----------------
__device__ __forceinline__ uint32_t smem_u32(const void* p) {
    uint32_t a;
    asm("{ .reg .u64 t; cvta.to.shared.u64 t, %1; cvt.u32.u64 %0, t; }" : "=r"(a) : "l"(p));
    return a;
}
__device__ __forceinline__ void ldsm4(uint32_t* d, uint32_t addr) {
    asm volatile("ldmatrix.sync.aligned.m8n8.x4.shared.b16 {%0,%1,%2,%3}, [%4];"
                 : "=r"(d[0]), "=r"(d[1]), "=r"(d[2]), "=r"(d[3]) : "r"(addr));
}
__device__ __forceinline__ void mma16816(float* c, const uint32_t* a,
                                         uint32_t b0, uint32_t b1) {
    asm volatile("mma.sync.aligned.m16n8k16.row.col.f32.bf16.bf16.f32 "
                 "{%0,%1,%2,%3}, {%4,%5,%6,%7}, {%8,%9}, {%0,%1,%2,%3};"
                 : "+f"(c[0]), "+f"(c[1]), "+f"(c[2]), "+f"(c[3])
                 : "r"(a[0]), "r"(a[1]), "r"(a[2]), "r"(a[3]), "r"(b0), "r"(b1));
}
__device__ __forceinline__ void cp_async16(uint32_t smem_dst, const void* gsrc) {
    asm volatile("cp.async.cg.shared.global [%0], [%1], 16;"
                 :: "r"(smem_dst), "l"(__cvta_generic_to_global(gsrc)) : "memory");
}
#define CP_COMMIT() asm volatile("cp.async.commit_group;" ::: "memory")
#define CP_WAIT0()  asm volatile("cp.async.wait_group 0;" ::: "memory")

__device__ __forceinline__ uint32_t pack_bf2(float x, float y) {
    __nv_bfloat162 t(__float2bfloat16(x), __float2bfloat16(y));
    return *reinterpret_cast<uint32_t*>(&t);
}

// ---------------- pre-kernel: split + transpose W ----------------
__global__ void wt_split_kernel(const float* __restrict__ wk) {
    int idx = blockIdx.x * 256 + threadIdx.x;
    if (idx < N_DIM * K_DIM) {
        int n = idx / K_DIM;
        int k = idx % K_DIM;
        float v = wk[(size_t)k * N_DIM + n];
        __nv_bfloat16 hi = __float2bfloat16(v);
        g_Wt_hi[idx] = hi;
        g_Wt_lo[idx] = __float2bfloat16(v - __bfloat162float(hi));
    }
}

// issue 12 MMAs for one B group-pair slot: term-major so same-acc distance = 8
#define MMA_BLOCK(AH, AL, BH0, BH1, BL0, BL1, ACCBASE)                       \
    do {                                                                     \
        mma16816(acc[0][(ACCBASE) + 0], AH[0], BH0[0], BH0[1]);              \
        mma16816(acc[1][(ACCBASE) + 0], AH[1], BH0[0], BH0[1]);              \
        mma16816(acc[0][(ACCBASE) + 1], AH[0], BH0[2], BH0[3]);              \
        mma16816(acc[1][(ACCBASE) + 1], AH[1], BH0[2], BH0[3]);              \
        mma16816(acc[0][(ACCBASE) + 2], AH[0], BH1[0], BH1[1]);              \
        mma16816(acc[1][(ACCBASE) + 2], AH[1], BH1[0], BH1[1]);              \
        mma16816(acc[0][(ACCBASE) + 3], AH[0], BH1[2], BH1[3]);              \
        mma16816(acc[1][(ACCBASE) + 3], AH[1], BH1[2], BH1[3]);              \
        mma16816(acc[0][(ACCBASE) + 0], AL[0], BH0[0], BH0[1]);              \
        mma16816(acc[1][(ACCBASE) + 0], AL[1], BH0[0], BH0[1]);              \
        mma16816(acc[0][(ACCBASE) + 1], AL[0], BH0[2], BH0[3]);              \
        mma16816(acc[1][(ACCBASE) + 1], AL[1], BH0[2], BH0[3]);              \
        mma16816(acc[0][(ACCBASE) + 2], AL[0], BH1[0], BH1[1]);              \
        mma16816(acc[1][(ACCBASE) + 2], AL[1], BH1[0], BH1[1]);              \
        mma16816(acc[0][(ACCBASE) + 3], AL[0], BH1[2], BH1[3]);              \
        mma16816(acc[1][(ACCBASE) + 3], AL[1], BH1[2], BH1[3]);              \
        mma16816(acc[0][(ACCBASE) + 0], AH[0], BL0[0], BL0[1]);              \
        mma16816(acc[1][(ACCBASE) + 0], AH[1], BL0[0], BL0[1]);              \
        mma16816(acc[0][(ACCBASE) + 1], AH[0], BL0[2], BL0[3]);              \
        mma16816(acc[1][(ACCBASE) + 1], AH[1], BL0[2], BL0[3]);              \
        mma16816(acc[0][(ACCBASE) + 2], AH[0], BL1[0], BL1[1]);              \
        mma16816(acc[1][(ACCBASE) + 2], AH[1], BL1[0], BL1[1]);              \
        mma16816(acc[0][(ACCBASE) + 3], AH[0], BL1[2], BL1[3]);              \
        mma16816(acc[1][(ACCBASE) + 3], AH[1], BL1[2], BL1[3]);              \
    } while (0)

// ---------------- main fused kernel ----------------
__global__ void __launch_bounds__(NTHREAD, 1)
caps_hmma_kernel(const float* __restrict__ inp, float* __restrict__ dout, int rows)
{
    extern __shared__ char smem[];
    const uint32_t sb = smem_u32(smem);
    const int tid  = threadIdx.x;
    const int lane = tid & 31;
    const int w    = tid >> 5;
    const int rowBase = blockIdx.x * BM;

    // warp tiling: 4 M-groups x 2 N-groups, warp tile 32x80
    const int m0 = (w >> 1) * 32;
    const int n0 = (w & 1) * 80;

    // ldmatrix per-lane offsets (bytes), rows stride 80B
    const int rA = (lane & 7) + ((lane >> 3) & 1) * 8;
    const int cA = (lane >> 4) * 16;
    const int aoff = (m0 + rA) * 80 + cA;

    const int rB = (lane & 7) + ((lane >> 4) ? 8 : 0);
    const int cB = ((lane >> 3) & 1) * 16;
    const int boff = (n0 + rB) * 80 + cB;

    float acc[2][10][4];
    #pragma unroll
    for (int mt = 0; mt < 2; ++mt)
        #pragma unroll
        for (int j = 0; j < 10; ++j)
            #pragma unroll
            for (int e = 0; e < 4; ++e) acc[mt][j][e] = 0.0f;

    // A global-load mapping: 4 float4 per thread per chunk (128 rows x 32 fp32)
    const int arow = tid >> 1;            // 0..127
    const int aseg0 = (tid & 1) * 4;      // float4 seg base 0 or 4

    // ---- prologue: fill stage 0 with chunk 0 ----
    {
        char* st = smem;
        #pragma unroll
        for (int j = 0; j < 4; ++j) {
            const int seg = aseg0 + j;
            float4 v = *reinterpret_cast<const float4*>(
                inp + (size_t)(rowBase + arow) * K_DIM + seg * 4);
            uint2 hp = make_uint2(pack_bf2(v.x, v.y), pack_bf2(v.z, v.w));
            float lx = v.x - __bfloat162float(__float2bfloat16(v.x));
            float ly = v.y - __bfloat162float(__float2bfloat16(v.y));
            float lz = v.z - __bfloat162float(__float2bfloat16(v.z));
            float lw = v.w - __bfloat162float(__float2bfloat16(v.w));
            uint2 lp = make_uint2(pack_bf2(lx, ly), pack_bf2(lz, lw));
            *reinterpret_cast<uint2*>(st + A_HI + arow * 80 + seg * 8) = hp;
            *reinterpret_cast<uint2*>(st + A_LO + arow * 80 + seg * 8) = lp;
        }
        #pragma unroll
        for (int i = 0; i < 5; ++i) {
            const int u = tid + 256 * i;          // 0..1279
            const int isLo = (u >= 640);
            const int r = isLo ? (u - 640) : u;
            const int n = r >> 2, seg = r & 3;
            const __nv_bfloat16* src = (isLo ? g_Wt_lo : g_Wt_hi) +
                                       (size_t)n * K_DIM + seg * 8;
            cp_async16(sb + (isLo ? B_LO : B_HI) + n * 80 + seg * 16, src);
        }
        CP_COMMIT();
        CP_WAIT0();
    }
    __syncthreads();

    // ---- main loop ----
    for (int c = 0; c < NCHUNK; ++c) {
        const int s = c & 1;
        const uint32_t cur = sb + s * STAGE_BYTES;
        const uint32_t nxt = sb + (s ^ 1) * STAGE_BYTES;
        char* nxtp = smem + (s ^ 1) * STAGE_BYTES;

        float4 ra[4];
        if (c + 1 < NCHUNK) {
            const int kbase = (c + 1) * BK;
            #pragma unroll
            for (int j = 0; j < 4; ++j)
                ra[j] = *reinterpret_cast<const float4*>(
                    inp + (size_t)(rowBase + arow) * K_DIM + kbase + (aseg0 + j) * 4);
            #pragma unroll
            for (int i = 0; i < 5; ++i) {
                const int u = tid + 256 * i;
                const int isLo = (u >= 640);
                const int r = isLo ? (u - 640) : u;
                const int n = r >> 2, seg = r & 3;
                const __nv_bfloat16* src = (isLo ? g_Wt_lo : g_Wt_hi) +
                                           (size_t)n * K_DIM + kbase + seg * 8;
                cp_async16(nxt + (isLo ? B_LO : B_HI) + n * 80 + seg * 16, src);
            }
            CP_COMMIT();
        }

        // ---- compute chunk c ----
        const uint32_t ah_base = cur + A_HI + aoff;
        const uint32_t al_base = cur + A_LO + aoff;
        const uint32_t bh_base = cur + B_HI + boff;
        const uint32_t bl_base = cur + B_LO + boff;
        #pragma unroll
        for (int ks = 0; ks < 2; ++ks) {
            uint32_t ah[2][4], al[2][4];
            ldsm4(ah[0], ah_base + ks * 32);
            ldsm4(ah[1], ah_base + 1280 + ks * 32);   // +16 rows
            ldsm4(al[0], al_base + ks * 32);
            ldsm4(al[1], al_base + 1280 + ks * 32);

            // group pair (0,1)
            {
                uint32_t bh0[4], bh1[4], bl0[4], bl1[4];
                ldsm4(bh0, bh_base + 0 * 1280 + ks * 32);
                ldsm4(bh1, bh_base + 1 * 1280 + ks * 32);
                ldsm4(bl0, bl_base + 0 * 1280 + ks * 32);
                ldsm4(bl1, bl_base + 1 * 1280 + ks * 32);
                MMA_BLOCK(ah, al, bh0, bh1, bl0, bl1, 0);
            }
            // group pair (2,3)
            {
                uint32_t bh0[4], bh1[4], bl0[4], bl1[4];
                ldsm4(bh0, bh_base + 2 * 1280 + ks * 32);
                ldsm4(bh1, bh_base + 3 * 1280 + ks * 32);
                ldsm4(bl0, bl_base + 2 * 1280 + ks * 32);
                ldsm4(bl1, bl_base + 3 * 1280 + ks * 32);
                MMA_BLOCK(ah, al, bh0, bh1, bl0, bl1, 4);
            }
            // group 4 (single)
            {
                uint32_t bh0[4], bl0[4];
                ldsm4(bh0, bh_base + 4 * 1280 + ks * 32);
                ldsm4(bl0, bl_base + 4 * 1280 + ks * 32);
                mma16816(acc[0][8], ah[0], bh0[0], bh0[1]);
                mma16816(acc[1][8], ah[1], bh0[0], bh0[1]);
                mma16816(acc[0][9], ah[0], bh0[2], bh0[3]);
                mma16816(acc[1][9], ah[1], bh0[2], bh0[3]);
                mma16816(acc[0][8], al[0], bh0[0], bh0[1]);
                mma16816(acc[1][8], al[1], bh0[0], bh0[1]);
                mma16816(acc[0][9], al[0], bh0[2], bh0[3]);
                mma16816(acc[1][9], al[1], bh0[2], bh0[3]);
                mma16816(acc[0][8], ah[0], bl0[0], bl0[1]);
                mma16816(acc[1][8], ah[1], bl0[0], bl0[1]);
                mma16816(acc[0][9], ah[0], bl0[2], bl0[3]);
                mma16816(acc[1][9], ah[1], bl0[2], bl0[3]);
            }
        }

        if (c + 1 < NCHUNK) {
            #pragma unroll
            for (int j = 0; j < 4; ++j) {
                const int seg = aseg0 + j;
                float4 v = ra[j];
                uint2 hp = make_uint2(pack_bf2(v.x, v.y), pack_bf2(v.z, v.w));
                float lx = v.x - __bfloat162float(__float2bfloat16(v.x));
                float ly = v.y - __bfloat162float(__float2bfloat16(v.y));
                float lz = v.z - __bfloat162float(__float2bfloat16(v.z));
                float lw = v.w - __bfloat162float(__float2bfloat16(v.w));
                uint2 lp = make_uint2(pack_bf2(lx, ly), pack_bf2(lz, lw));
                *reinterpret_cast<uint2*>(nxtp + A_HI + arow * 80 + seg * 8) = hp;
                *reinterpret_cast<uint2*>(nxtp + A_LO + arow * 80 + seg * 8) = lp;
            }
            CP_WAIT0();
        }
        __syncthreads();
    }

    // ---- write C frags to padded smem hat tile ----
    float* hat = reinterpret_cast<float*>(smem);
    {
        const int cbase = n0 + (lane & 3) * 2;
        #pragma unroll
        for (int mt = 0; mt < 2; ++mt) {
            const int r0 = m0 + mt * 16 + (lane >> 2);
            #pragma unroll
            for (int j = 0; j < 10; ++j) {
                const int col = cbase + 8 * j;
                hat[r0 * HAT_STRIDE + col]           = acc[mt][j][0];
                hat[r0 * HAT_STRIDE + col + 1]       = acc[mt][j][1];
                hat[(r0 + 8) * HAT_STRIDE + col]     = acc[mt][j][2];
                hat[(r0 + 8) * HAT_STRIDE + col + 1] = acc[mt][j][3];
            }
        }
    }
    __syncthreads();

    // ---- dynamic routing: one thread per row ----
    if (tid < BM) {
        const float* h = &hat[tid * HAT_STRIDE];

        float b[NC];
        #pragma unroll
        for (int n = 0; n < NC; ++n) b[n] = 0.0f;
        float out[DC];

        #pragma unroll
        for (int it = 0; it < 3; ++it) {
            float m = b[0];
            #pragma unroll
            for (int n = 1; n < NC; ++n) m = fmaxf(m, b[n]);
            float cc[NC];
            float se = 0.0f;
            #pragma unroll
            for (int n = 0; n < NC; ++n) { cc[n] = expf(b[n] - m); se += cc[n]; }
            const float inv = 1.0f / se;

            float s[DC];
            #pragma unroll
            for (int d = 0; d < DC; ++d) s[d] = 0.0f;
            #pragma unroll
            for (int n = 0; n < NC; ++n) {
                const float cn = cc[n] * inv;
                #pragma unroll
                for (int d = 0; d < DC; ++d)
                    s[d] = fmaf(cn, h[n * DC + d], s[d]);
            }

            float s2 = 0.0f;
            #pragma unroll
            for (int d = 0; d < DC; ++d) s2 = fmaf(s[d], s[d], s2);
            const float scale = s2 / ((1.0f + s2) * sqrtf(s2 + 1e-7f));
            #pragma unroll
            for (int d = 0; d < DC; ++d) out[d] = scale * s[d];

            if (it < 2) {
                #pragma unroll
                for (int n = 0; n < NC; ++n) {
                    float dot = 0.0f;
                    #pragma unroll
                    for (int d = 0; d < DC; ++d)
                        dot = fmaf(h[n * DC + d], out[d], dot);
                    b[n] += dot;
                }
            }
        }

        float4* o = reinterpret_cast<float4*>(dout + (size_t)(rowBase + tid) * DC);
        o[0] = make_float4(out[0],  out[1],  out[2],  out[3]);
        o[1] = make_float4(out[4],  out[5],  out[6],  out[7]);
        o[2] = make_float4(out[8],  out[9],  out[10], out[11]);
        o[3] = make_float4(out[12], out[13], out[14], out[15]);
    }
}

extern "C" void kernel_launch(void* const* d_in, const int* in_sizes, int n_in,
                              void* d_out, int out_size)
{
    const float* inp = (const float*)d_in[0];
    const float* wk  = (const float*)d_in[1];
    float* out       = (float*)d_out;

    const int rows = in_sizes[0] / K_DIM;   // 16384

    wt_split_kernel<<<(N_DIM * K_DIM + 255) / 256, 256>>>(wk);

    cudaFuncSetAttribute(caps_hmma_kernel,
                         cudaFuncAttributeMaxDynamicSharedMemorySize, SMEM_TOTAL);
    caps_hmma_kernel<<<rows / BM, NTHREAD, SMEM_TOTAL>>>(inp, out, rows);
}